// round 1
// baseline (speedup 1.0000x reference)
#include <cuda_runtime.h>
#include <cuda_bf16.h>
#include <math.h>

// ---------------------------------------------------------------------------
// RGAT (DGL-style), 3 hetero layers x 2 edge types of GATConv (H=4, D=128),
// then final linear [512 -> 2983].
// fp32 baseline: tiled SGEMM + atomic edge-softmax + atomic scatter.
// ---------------------------------------------------------------------------

#define NN     40000           // nodes
#define EE     150000          // edges per type
#define HH     4               // heads
#define DD     128             // dim per head
#define FF     512             // H*D
#define NT     2               // edge types

// ------------------------- scratch (device globals) ------------------------
__device__ float g_feat[NT * NN * FF];   // per-type features after GEMM
__device__ float g_acc [NT * NN * FF];   // per-type aggregation output
__device__ float g_h   [NN * FF];        // layer output / next layer input
__device__ float g_el  [NT * NN * HH];
__device__ float g_er  [NT * NN * HH];
__device__ float g_m   [NT * NN * HH];   // segment max
__device__ float g_s   [NT * NN * HH];   // segment sum
__device__ float g_w   [NT * EE * HH];   // exp(e - m)

// ------------------------------ helpers ------------------------------------
__device__ __forceinline__ float leaky02(float x) { return x > 0.f ? x : 0.2f * x; }
__device__ __forceinline__ float leaky01(float x) { return x > 0.f ? x : 0.01f * x; }

// float atomic max via signed/unsigned monotonicity trick (no NaNs here)
__device__ __forceinline__ void atomicMaxF(float* addr, float v) {
    if (v >= 0.f) atomicMax((int*)addr, __float_as_int(v));
    else          atomicMin((unsigned int*)addr, __float_as_uint(v));
}

// ------------------------------ SGEMM --------------------------------------
// C[M,N] = A[M,K] @ B[K,N] (+ bias[N]).  BM=BN=128, BK=8, 8x8 per thread.
// K must be a multiple of 8 (1024 / 512 here). A rows must be 16B aligned.
__global__ __launch_bounds__(256)
void sgemm128(const float* __restrict__ A, const float* __restrict__ B,
              float* __restrict__ C, int M, int N, int K,
              const float* __restrict__ bias)
{
    __shared__ float As[8][128];
    __shared__ float Bs[8][128];

    const int tid  = threadIdx.x;          // 0..255
    const int tx   = tid & 15;             // 16 thread cols
    const int ty   = tid >> 4;             // 16 thread rows
    const int row0 = blockIdx.y * 128;
    const int col0 = blockIdx.x * 128;

    float acc[8][8];
#pragma unroll
    for (int i = 0; i < 8; i++)
#pragma unroll
        for (int j = 0; j < 8; j++) acc[i][j] = 0.f;

    const int am = tid >> 1;               // 0..127 (A tile row)
    const int ak = (tid & 1) * 4;          // 0 or 4 (A tile k)

    for (int k0 = 0; k0 < K; k0 += 8) {
        // load A tile (128 x 8), one float4 per thread
        float4 av = make_float4(0.f, 0.f, 0.f, 0.f);
        int arow = row0 + am;
        if (arow < M)
            av = *(const float4*)(A + (size_t)arow * K + k0 + ak);
        As[ak + 0][am] = av.x;
        As[ak + 1][am] = av.y;
        As[ak + 2][am] = av.z;
        As[ak + 3][am] = av.w;

        // load B tile (8 x 128), 4 scalars per thread, coalesced along N
#pragma unroll
        for (int i = 0; i < 4; i++) {
            int e = tid + 256 * i;
            int r = e >> 7;
            int c = e & 127;
            int bc = col0 + c;
            Bs[r][c] = (bc < N) ? B[(size_t)(k0 + r) * N + bc] : 0.f;
        }
        __syncthreads();

#pragma unroll
        for (int kk = 0; kk < 8; kk++) {
            float a_[8], b_[8];
#pragma unroll
            for (int i = 0; i < 8; i++) a_[i] = As[kk][ty * 8 + i];
#pragma unroll
            for (int j = 0; j < 8; j++) b_[j] = Bs[kk][tx * 8 + j];
#pragma unroll
            for (int i = 0; i < 8; i++)
#pragma unroll
                for (int j = 0; j < 8; j++)
                    acc[i][j] += a_[i] * b_[j];
        }
        __syncthreads();
    }

#pragma unroll
    for (int i = 0; i < 8; i++) {
        int r = row0 + ty * 8 + i;
        if (r >= M) continue;
#pragma unroll
        for (int j = 0; j < 8; j++) {
            int c = col0 + tx * 8 + j;
            if (c < N) {
                float v = acc[i][j];
                if (bias) v += bias[c];
                C[(size_t)r * N + c] = v;
            }
        }
    }
}

// ------------------------ el / er (attention dots) --------------------------
// one block (128 threads) per node; warp w handles head w.
__global__ void eler_kernel(const float* __restrict__ feat,
                            const float* __restrict__ al,
                            const float* __restrict__ ar,
                            float* __restrict__ el, float* __restrict__ er)
{
    const int n   = blockIdx.x;
    const int tid = threadIdx.x;            // 0..127
    float4 f = *(const float4*)(feat + (size_t)n * FF + tid * 4);
    float4 a = *(const float4*)(al + tid * 4);
    float4 r = *(const float4*)(ar + tid * 4);
    float vl = f.x * a.x + f.y * a.y + f.z * a.z + f.w * a.w;
    float vr = f.x * r.x + f.y * r.y + f.z * r.z + f.w * r.w;
#pragma unroll
    for (int o = 16; o > 0; o >>= 1) {
        vl += __shfl_down_sync(0xffffffffu, vl, o);
        vr += __shfl_down_sync(0xffffffffu, vr, o);
    }
    if ((tid & 31) == 0) {
        int h = tid >> 5;
        el[n * HH + h] = vl;
        er[n * HH + h] = vr;
    }
}

// ------------------------------ fill -inf ----------------------------------
__global__ void fill_neginf(float* __restrict__ p, int n)
{
    int i = blockIdx.x * blockDim.x + threadIdx.x;
    if (i < n) p[i] = -INFINITY;
}

// ------------------------- edge pass A: segment max -------------------------
__global__ void edge_max_kernel(const int* __restrict__ src, const int* __restrict__ dst,
                                const float* __restrict__ el, const float* __restrict__ er,
                                float* __restrict__ m, int E)
{
    int e = blockIdx.x * blockDim.x + threadIdx.x;
    if (e >= E) return;
    int s = src[e], d = dst[e];
    float4 l = *(const float4*)(el + s * HH);
    float4 r = *(const float4*)(er + d * HH);
    float v0 = leaky02(l.x + r.x);
    float v1 = leaky02(l.y + r.y);
    float v2 = leaky02(l.z + r.z);
    float v3 = leaky02(l.w + r.w);
    atomicMaxF(&m[d * HH + 0], v0);
    atomicMaxF(&m[d * HH + 1], v1);
    atomicMaxF(&m[d * HH + 2], v2);
    atomicMaxF(&m[d * HH + 3], v3);
}

// ---------------------- edge pass B: exp + segment sum ----------------------
__global__ void edge_expsum_kernel(const int* __restrict__ src, const int* __restrict__ dst,
                                   const float* __restrict__ el, const float* __restrict__ er,
                                   const float* __restrict__ m,
                                   float* __restrict__ w, float* __restrict__ ssum, int E)
{
    int e = blockIdx.x * blockDim.x + threadIdx.x;
    if (e >= E) return;
    int s = src[e], d = dst[e];
    float4 l  = *(const float4*)(el + s * HH);
    float4 r  = *(const float4*)(er + d * HH);
    float4 mx = *(const float4*)(m + d * HH);
    float w0 = expf(leaky02(l.x + r.x) - mx.x);
    float w1 = expf(leaky02(l.y + r.y) - mx.y);
    float w2 = expf(leaky02(l.z + r.z) - mx.z);
    float w3 = expf(leaky02(l.w + r.w) - mx.w);
    *(float4*)(w + (size_t)e * HH) = make_float4(w0, w1, w2, w3);
    atomicAdd(&ssum[d * HH + 0], w0);
    atomicAdd(&ssum[d * HH + 1], w1);
    atomicAdd(&ssum[d * HH + 2], w2);
    atomicAdd(&ssum[d * HH + 3], w3);
}

// ------------------- edge pass C: normalized scatter-add ---------------------
// one thread per (edge, float4 of the 512-wide row): E*128 threads
__global__ void edge_scatter_kernel(const int* __restrict__ src, const int* __restrict__ dst,
                                    const float* __restrict__ feat,
                                    const float* __restrict__ w, const float* __restrict__ ssum,
                                    float* __restrict__ acc, int E)
{
    long long i = (long long)blockIdx.x * blockDim.x + threadIdx.x;
    long long total = (long long)E * 128;
    if (i >= total) return;
    int e = (int)(i >> 7);
    int j = (int)(i & 127);          // which float4 of the row
    int h = j >> 5;                  // 32 float4s per head
    int s = src[e], d = dst[e];
    float a = w[(size_t)e * HH + h] / ssum[d * HH + h];
    float4 f = *(const float4*)(feat + (size_t)s * FF + j * 4);
    float* o = acc + (size_t)d * FF + j * 4;
    atomicAdd(o + 0, f.x * a);
    atomicAdd(o + 1, f.y * a);
    atomicAdd(o + 2, f.z * a);
    atomicAdd(o + 3, f.w * a);
}

// ----------------------- combine types (+bias, +act) ------------------------
__global__ void combine_kernel(const float* __restrict__ acc0, const float* __restrict__ acc1,
                               const float* __restrict__ b0, const float* __restrict__ b1,
                               float* __restrict__ out, int total, int act)
{
    int i = blockIdx.x * blockDim.x + threadIdx.x;
    if (i >= total) return;
    int j = i & (FF - 1);
    float v0 = acc0[i] + b0[j];
    float v1 = acc1[i] + b1[j];
    if (act) { v0 = leaky01(v0); v1 = leaky01(v1); }
    out[i] = v0 + v1;
}

// ------------------------------ host driver --------------------------------
extern "C" void kernel_launch(void* const* d_in, const int* in_sizes, int n_in,
                              void* d_out, int out_size)
{
    const float* x    = (const float*)d_in[0];
    const int*   srcA[NT] = { (const int*)d_in[1], (const int*)d_in[3] };
    const int*   dstA[NT] = { (const int*)d_in[2], (const int*)d_in[4] };
    const float* W[3]  = { (const float*)d_in[5],  (const float*)d_in[9],  (const float*)d_in[13] };
    const float* al[3] = { (const float*)d_in[6],  (const float*)d_in[10], (const float*)d_in[14] };
    const float* ar[3] = { (const float*)d_in[7],  (const float*)d_in[11], (const float*)d_in[15] };
    const float* bb[3] = { (const float*)d_in[8],  (const float*)d_in[12], (const float*)d_in[16] };
    const float* Wout  = (const float*)d_in[17];
    const float* bout  = (const float*)d_in[18];

    const int E = in_sizes[1];                      // 150000
    const int M = in_sizes[0] / 1024;               // 40000

    // scratch pointers
    void* p;
    cudaGetSymbolAddress(&p, g_feat); float* feat = (float*)p;
    cudaGetSymbolAddress(&p, g_acc ); float* acc  = (float*)p;
    cudaGetSymbolAddress(&p, g_h   ); float* hbuf = (float*)p;
    cudaGetSymbolAddress(&p, g_el  ); float* el   = (float*)p;
    cudaGetSymbolAddress(&p, g_er  ); float* er   = (float*)p;
    cudaGetSymbolAddress(&p, g_m   ); float* mm   = (float*)p;
    cudaGetSymbolAddress(&p, g_s   ); float* ss   = (float*)p;
    cudaGetSymbolAddress(&p, g_w   ); float* ww   = (float*)p;

    const size_t NF  = (size_t)M * FF;              // per-type feature block
    const size_t NH4 = (size_t)M * HH;
    const size_t EH4 = (size_t)E * HH;

    const float* hin = x;
    int K = 1024;

    for (int l = 0; l < 3; l++) {
        // 1) per-type GEMM: feat[t] = hin @ W[l][t]
        dim3 ggrid((FF + 127) / 128, (M + 127) / 128);
        for (int t = 0; t < NT; t++)
            sgemm128<<<ggrid, 256>>>(hin, W[l] + (size_t)t * K * FF,
                                     feat + t * NF, M, FF, K, nullptr);

        // 2) attention dots el / er
        for (int t = 0; t < NT; t++)
            eler_kernel<<<M, 128>>>(feat + t * NF,
                                    al[l] + t * FF, ar[l] + t * FF,
                                    el + t * NH4, er + t * NH4);

        // 3) init reductions
        {
            int n = NT * (int)NH4;
            fill_neginf<<<(n + 255) / 256, 256>>>(mm, n);
            cudaMemsetAsync(ss, 0, (size_t)NT * NH4 * sizeof(float));
            cudaMemsetAsync(acc, 0, (size_t)NT * NF * sizeof(float));
        }

        // 4) edge softmax + scatter, per type
        for (int t = 0; t < NT; t++) {
            int eb = (E + 255) / 256;
            edge_max_kernel<<<eb, 256>>>(srcA[t], dstA[t],
                                         el + t * NH4, er + t * NH4,
                                         mm + t * NH4, E);
            edge_expsum_kernel<<<eb, 256>>>(srcA[t], dstA[t],
                                            el + t * NH4, er + t * NH4,
                                            mm + t * NH4,
                                            ww + t * EH4, ss + t * NH4, E);
            long long tot = (long long)E * 128;
            int sb = (int)((tot + 255) / 256);
            edge_scatter_kernel<<<sb, 256>>>(srcA[t], dstA[t],
                                             feat + t * NF,
                                             ww + t * EH4, ss + t * NH4,
                                             acc + t * NF, E);
        }

        // 5) combine types (+bias, +leaky 0.01 except last layer)
        {
            int total = (int)NF;
            combine_kernel<<<(total + 255) / 256, 256>>>(
                acc, acc + NF, bb[l], bb[l] + FF, hbuf, total, l < 2 ? 1 : 0);
        }

        hin = hbuf;
        K = FF;
    }

    // final projection: out = h @ Wout + bout   [M, 2983]
    const int NOUT = out_size / M;                   // 2983
    dim3 fgrid((NOUT + 127) / 128, (M + 127) / 128);
    sgemm128<<<fgrid, 256>>>(hbuf, Wout, (float*)d_out, M, NOUT, FF, bout);
}

// round 2
// speedup vs baseline: 1.0518x; 1.0518x over previous
#include <cuda_runtime.h>
#include <cuda_bf16.h>
#include <math.h>

// ---------------------------------------------------------------------------
// RGAT (DGL-style), 3 hetero layers x 2 edge types of GATConv (H=4, D=128),
// then final linear [512 -> 2983].
// Round 2: SGEMM inner loop converted to packed fp32 (fma.rn.f32x2 / FFMA2),
// the sm_103a dual-fp32 path. Everything else unchanged.
// ---------------------------------------------------------------------------

#define NN     40000           // nodes
#define EE     150000          // edges per type
#define HH     4               // heads
#define DD     128             // dim per head
#define FF     512             // H*D
#define NT     2               // edge types

// ------------------------- scratch (device globals) ------------------------
__device__ float g_feat[NT * NN * FF];   // per-type features after GEMM
__device__ float g_acc [NT * NN * FF];   // per-type aggregation output
__device__ float g_h   [NN * FF];        // layer output / next layer input
__device__ float g_el  [NT * NN * HH];
__device__ float g_er  [NT * NN * HH];
__device__ float g_m   [NT * NN * HH];   // segment max
__device__ float g_s   [NT * NN * HH];   // segment sum
__device__ float g_w   [NT * EE * HH];   // exp(e - m)

// ------------------------------ helpers ------------------------------------
__device__ __forceinline__ float leaky02(float x) { return x > 0.f ? x : 0.2f * x; }
__device__ __forceinline__ float leaky01(float x) { return x > 0.f ? x : 0.01f * x; }

__device__ __forceinline__ void atomicMaxF(float* addr, float v) {
    if (v >= 0.f) atomicMax((int*)addr, __float_as_int(v));
    else          atomicMin((unsigned int*)addr, __float_as_uint(v));
}

// --------------------- packed fp32 (f32x2) primitives -----------------------
__device__ __forceinline__ unsigned long long pack2(float x) {
    unsigned long long r;
    asm("mov.b64 %0, {%1, %1};" : "=l"(r) : "f"(x));
    return r;
}
__device__ __forceinline__ void fma2(unsigned long long& d,
                                     unsigned long long a, unsigned long long b) {
    asm("fma.rn.f32x2 %0, %1, %2, %0;" : "+l"(d) : "l"(a), "l"(b));
}
__device__ __forceinline__ float2 unpack2(unsigned long long v) {
    float lo, hi;
    asm("mov.b64 {%0, %1}, %2;" : "=f"(lo), "=f"(hi) : "l"(v));
    return make_float2(lo, hi);
}

// ------------------------------ SGEMM --------------------------------------
// C[M,N] = A[M,K] @ B[K,N] (+ bias[N]).  BM=BN=128, BK=8, 8x8 per thread.
// Inner product uses FFMA2 (2 fp32 lanes per issue).
__global__ __launch_bounds__(256)
void sgemm128(const float* __restrict__ A, const float* __restrict__ B,
              float* __restrict__ C, int M, int N, int K,
              const float* __restrict__ bias)
{
    __shared__ __align__(16) float As[8][128];
    __shared__ __align__(16) float Bs[8][128];

    const int tid  = threadIdx.x;          // 0..255
    const int tx   = tid & 15;             // 16 thread cols
    const int ty   = tid >> 4;             // 16 thread rows
    const int row0 = blockIdx.y * 128;
    const int col0 = blockIdx.x * 128;

    unsigned long long acc2[8][4];         // 8 rows x 4 col-pairs
#pragma unroll
    for (int i = 0; i < 8; i++)
#pragma unroll
        for (int j = 0; j < 4; j++) acc2[i][j] = 0ull;

    const int am = tid >> 1;               // 0..127 (A tile row)
    const int ak = (tid & 1) * 4;          // 0 or 4 (A tile k)

    for (int k0 = 0; k0 < K; k0 += 8) {
        // load A tile (128 x 8), one float4 per thread
        float4 av = make_float4(0.f, 0.f, 0.f, 0.f);
        int arow = row0 + am;
        if (arow < M)
            av = *(const float4*)(A + (size_t)arow * K + k0 + ak);
        As[ak + 0][am] = av.x;
        As[ak + 1][am] = av.y;
        As[ak + 2][am] = av.z;
        As[ak + 3][am] = av.w;

        // load B tile (8 x 128), 4 scalars per thread, coalesced along N
#pragma unroll
        for (int i = 0; i < 4; i++) {
            int e = tid + 256 * i;
            int r = e >> 7;
            int c = e & 127;
            int bc = col0 + c;
            Bs[r][c] = (bc < N) ? B[(size_t)(k0 + r) * N + bc] : 0.f;
        }
        __syncthreads();

#pragma unroll
        for (int kk = 0; kk < 8; kk++) {
            // B: 8 consecutive floats = 4 packed pairs (64-bit LDS)
            unsigned long long b2_[4];
            const unsigned long long* bp =
                (const unsigned long long*)&Bs[kk][tx * 8];
#pragma unroll
            for (int j = 0; j < 4; j++) b2_[j] = bp[j];

            // A: 8 scalars, broadcast-packed into both halves
            unsigned long long a2_[8];
#pragma unroll
            for (int i = 0; i < 8; i++) a2_[i] = pack2(As[kk][ty * 8 + i]);

#pragma unroll
            for (int i = 0; i < 8; i++)
#pragma unroll
                for (int j = 0; j < 4; j++)
                    fma2(acc2[i][j], a2_[i], b2_[j]);
        }
        __syncthreads();
    }

#pragma unroll
    for (int i = 0; i < 8; i++) {
        int r = row0 + ty * 8 + i;
        if (r >= M) continue;
#pragma unroll
        for (int j = 0; j < 4; j++) {
            float2 v = unpack2(acc2[i][j]);
            int c = col0 + tx * 8 + j * 2;
            if (c < N) {
                float o = v.x;
                if (bias) o += bias[c];
                C[(size_t)r * N + c] = o;
            }
            if (c + 1 < N) {
                float o = v.y;
                if (bias) o += bias[c + 1];
                C[(size_t)r * N + c + 1] = o;
            }
        }
    }
}

// ------------------------ el / er (attention dots) --------------------------
__global__ void eler_kernel(const float* __restrict__ feat,
                            const float* __restrict__ al,
                            const float* __restrict__ ar,
                            float* __restrict__ el, float* __restrict__ er)
{
    const int n   = blockIdx.x;
    const int tid = threadIdx.x;            // 0..127
    float4 f = *(const float4*)(feat + (size_t)n * FF + tid * 4);
    float4 a = *(const float4*)(al + tid * 4);
    float4 r = *(const float4*)(ar + tid * 4);
    float vl = f.x * a.x + f.y * a.y + f.z * a.z + f.w * a.w;
    float vr = f.x * r.x + f.y * r.y + f.z * r.z + f.w * r.w;
#pragma unroll
    for (int o = 16; o > 0; o >>= 1) {
        vl += __shfl_down_sync(0xffffffffu, vl, o);
        vr += __shfl_down_sync(0xffffffffu, vr, o);
    }
    if ((tid & 31) == 0) {
        int h = tid >> 5;
        el[n * HH + h] = vl;
        er[n * HH + h] = vr;
    }
}

// ------------------------------ fill -inf ----------------------------------
__global__ void fill_neginf(float* __restrict__ p, int n)
{
    int i = blockIdx.x * blockDim.x + threadIdx.x;
    if (i < n) p[i] = -INFINITY;
}

// ------------------------- edge pass A: segment max -------------------------
__global__ void edge_max_kernel(const int* __restrict__ src, const int* __restrict__ dst,
                                const float* __restrict__ el, const float* __restrict__ er,
                                float* __restrict__ m, int E)
{
    int e = blockIdx.x * blockDim.x + threadIdx.x;
    if (e >= E) return;
    int s = src[e], d = dst[e];
    float4 l = *(const float4*)(el + s * HH);
    float4 r = *(const float4*)(er + d * HH);
    atomicMaxF(&m[d * HH + 0], leaky02(l.x + r.x));
    atomicMaxF(&m[d * HH + 1], leaky02(l.y + r.y));
    atomicMaxF(&m[d * HH + 2], leaky02(l.z + r.z));
    atomicMaxF(&m[d * HH + 3], leaky02(l.w + r.w));
}

// ---------------------- edge pass B: exp + segment sum ----------------------
__global__ void edge_expsum_kernel(const int* __restrict__ src, const int* __restrict__ dst,
                                   const float* __restrict__ el, const float* __restrict__ er,
                                   const float* __restrict__ m,
                                   float* __restrict__ w, float* __restrict__ ssum, int E)
{
    int e = blockIdx.x * blockDim.x + threadIdx.x;
    if (e >= E) return;
    int s = src[e], d = dst[e];
    float4 l  = *(const float4*)(el + s * HH);
    float4 r  = *(const float4*)(er + d * HH);
    float4 mx = *(const float4*)(m + d * HH);
    float w0 = expf(leaky02(l.x + r.x) - mx.x);
    float w1 = expf(leaky02(l.y + r.y) - mx.y);
    float w2 = expf(leaky02(l.z + r.z) - mx.z);
    float w3 = expf(leaky02(l.w + r.w) - mx.w);
    *(float4*)(w + (size_t)e * HH) = make_float4(w0, w1, w2, w3);
    atomicAdd(&ssum[d * HH + 0], w0);
    atomicAdd(&ssum[d * HH + 1], w1);
    atomicAdd(&ssum[d * HH + 2], w2);
    atomicAdd(&ssum[d * HH + 3], w3);
}

// ------------------- edge pass C: normalized scatter-add ---------------------
__global__ void edge_scatter_kernel(const int* __restrict__ src, const int* __restrict__ dst,
                                    const float* __restrict__ feat,
                                    const float* __restrict__ w, const float* __restrict__ ssum,
                                    float* __restrict__ acc, int E)
{
    long long i = (long long)blockIdx.x * blockDim.x + threadIdx.x;
    long long total = (long long)E * 128;
    if (i >= total) return;
    int e = (int)(i >> 7);
    int j = (int)(i & 127);          // which float4 of the row
    int h = j >> 5;                  // 32 float4s per head
    int s = src[e], d = dst[e];
    float a = w[(size_t)e * HH + h] / ssum[d * HH + h];
    float4 f = *(const float4*)(feat + (size_t)s * FF + j * 4);
    float* o = acc + (size_t)d * FF + j * 4;
    atomicAdd(o + 0, f.x * a);
    atomicAdd(o + 1, f.y * a);
    atomicAdd(o + 2, f.z * a);
    atomicAdd(o + 3, f.w * a);
}

// ----------------------- combine types (+bias, +act) ------------------------
__global__ void combine_kernel(const float* __restrict__ acc0, const float* __restrict__ acc1,
                               const float* __restrict__ b0, const float* __restrict__ b1,
                               float* __restrict__ out, int total, int act)
{
    int i = blockIdx.x * blockDim.x + threadIdx.x;
    if (i >= total) return;
    int j = i & (FF - 1);
    float v0 = acc0[i] + b0[j];
    float v1 = acc1[i] + b1[j];
    if (act) { v0 = leaky01(v0); v1 = leaky01(v1); }
    out[i] = v0 + v1;
}

// ------------------------------ host driver --------------------------------
extern "C" void kernel_launch(void* const* d_in, const int* in_sizes, int n_in,
                              void* d_out, int out_size)
{
    const float* x    = (const float*)d_in[0];
    const int*   srcA[NT] = { (const int*)d_in[1], (const int*)d_in[3] };
    const int*   dstA[NT] = { (const int*)d_in[2], (const int*)d_in[4] };
    const float* W[3]  = { (const float*)d_in[5],  (const float*)d_in[9],  (const float*)d_in[13] };
    const float* al[3] = { (const float*)d_in[6],  (const float*)d_in[10], (const float*)d_in[14] };
    const float* ar[3] = { (const float*)d_in[7],  (const float*)d_in[11], (const float*)d_in[15] };
    const float* bb[3] = { (const float*)d_in[8],  (const float*)d_in[12], (const float*)d_in[16] };
    const float* Wout  = (const float*)d_in[17];
    const float* bout  = (const float*)d_in[18];

    const int E = in_sizes[1];                      // 150000
    const int M = in_sizes[0] / 1024;               // 40000

    void* p;
    cudaGetSymbolAddress(&p, g_feat); float* feat = (float*)p;
    cudaGetSymbolAddress(&p, g_acc ); float* acc  = (float*)p;
    cudaGetSymbolAddress(&p, g_h   ); float* hbuf = (float*)p;
    cudaGetSymbolAddress(&p, g_el  ); float* el   = (float*)p;
    cudaGetSymbolAddress(&p, g_er  ); float* er   = (float*)p;
    cudaGetSymbolAddress(&p, g_m   ); float* mm   = (float*)p;
    cudaGetSymbolAddress(&p, g_s   ); float* ss   = (float*)p;
    cudaGetSymbolAddress(&p, g_w   ); float* ww   = (float*)p;

    const size_t NF  = (size_t)M * FF;
    const size_t NH4 = (size_t)M * HH;
    const size_t EH4 = (size_t)E * HH;

    const float* hin = x;
    int K = 1024;

    for (int l = 0; l < 3; l++) {
        // 1) per-type GEMM: feat[t] = hin @ W[l][t]
        dim3 ggrid((FF + 127) / 128, (M + 127) / 128);
        for (int t = 0; t < NT; t++)
            sgemm128<<<ggrid, 256>>>(hin, W[l] + (size_t)t * K * FF,
                                     feat + t * NF, M, FF, K, nullptr);

        // 2) attention dots el / er
        for (int t = 0; t < NT; t++)
            eler_kernel<<<M, 128>>>(feat + t * NF,
                                    al[l] + t * FF, ar[l] + t * FF,
                                    el + t * NH4, er + t * NH4);

        // 3) init reductions
        {
            int n = NT * (int)NH4;
            fill_neginf<<<(n + 255) / 256, 256>>>(mm, n);
            cudaMemsetAsync(ss, 0, (size_t)NT * NH4 * sizeof(float));
            cudaMemsetAsync(acc, 0, (size_t)NT * NF * sizeof(float));
        }

        // 4) edge softmax + scatter, per type
        for (int t = 0; t < NT; t++) {
            int eb = (E + 255) / 256;
            edge_max_kernel<<<eb, 256>>>(srcA[t], dstA[t],
                                         el + t * NH4, er + t * NH4,
                                         mm + t * NH4, E);
            edge_expsum_kernel<<<eb, 256>>>(srcA[t], dstA[t],
                                            el + t * NH4, er + t * NH4,
                                            mm + t * NH4,
                                            ww + t * EH4, ss + t * NH4, E);
            long long tot = (long long)E * 128;
            int sb = (int)((tot + 255) / 256);
            edge_scatter_kernel<<<sb, 256>>>(srcA[t], dstA[t],
                                             feat + t * NF,
                                             ww + t * EH4, ss + t * NH4,
                                             acc + t * NF, E);
        }

        // 5) combine types (+bias, +leaky 0.01 except last layer)
        {
            int total = (int)NF;
            combine_kernel<<<(total + 255) / 256, 256>>>(
                acc, acc + NF, bb[l], bb[l] + FF, hbuf, total, l < 2 ? 1 : 0);
        }

        hin = hbuf;
        K = FF;
    }

    // final projection: out = h @ Wout + bout   [M, 2983]
    const int NOUT = out_size / M;
    dim3 fgrid((NOUT + 127) / 128, (M + 127) / 128);
    sgemm128<<<fgrid, 256>>>(hbuf, Wout, (float*)d_out, M, NOUT, FF, bout);
}

// round 4
// speedup vs baseline: 2.0623x; 1.9608x over previous
#include <cuda_runtime.h>
#include <cuda_bf16.h>
#include <math.h>
#include <stdint.h>

// ---------------------------------------------------------------------------
// RGAT (DGL-style), 3 hetero layers x 2 edge types of GATConv (H=4, D=128),
// then final linear [512 -> 2983].
// Round 4: GEMMs on tensor cores via target-portable mma.sync (bf16, 3-pass
// hi/lo split for fp32-like accuracy), ldmatrix + cp.async double buffering.
// (tcgen05 PTX is rejected at the compute_103 PTX target this toolchain emits.)
// ---------------------------------------------------------------------------

#define NN     40000
#define EE     150000
#define HH     4
#define FF     512
#define NT     2
#define BTS    1527296        // transposed-weight buffer stride (2983*512 max)

// ------------------------- scratch (device globals) ------------------------
__device__ float g_feat[NT * NN * FF];
__device__ float g_acc [NT * NN * FF];
__device__ float g_h   [NN * FF];
__device__ float g_el  [NT * NN * HH];
__device__ float g_er  [NT * NN * HH];
__device__ float g_m   [NT * NN * HH];
__device__ float g_s   [NT * NN * HH];
__device__ float g_w   [NT * EE * HH];
__device__ unsigned short g_ah[NN * 1024];   // A hi (bf16 bits), K-major
__device__ unsigned short g_al[NN * 1024];   // A lo
__device__ unsigned short g_bth[NT * BTS];   // B^T hi  [N,K]
__device__ unsigned short g_btl[NT * BTS];   // B^T lo

// ------------------------------ helpers ------------------------------------
__device__ __forceinline__ float leaky02(float x) { return x > 0.f ? x : 0.2f * x; }
__device__ __forceinline__ float leaky01(float x) { return x > 0.f ? x : 0.01f * x; }
__device__ __forceinline__ void atomicMaxF(float* addr, float v) {
    if (v >= 0.f) atomicMax((int*)addr, __float_as_int(v));
    else          atomicMin((unsigned int*)addr, __float_as_uint(v));
}
__device__ __forceinline__ uint32_t smem_u32(const void* p) {
    uint32_t a;
    asm("{ .reg .u64 t; cvta.to.shared.u64 t, %1; cvt.u32.u64 %0, t; }"
        : "=r"(a) : "l"(p));
    return a;
}

// ------------------------ mma / ldmatrix / cp.async -------------------------
__device__ __forceinline__ void ldsm_x4(uint32_t& r0, uint32_t& r1,
                                        uint32_t& r2, uint32_t& r3, uint32_t addr) {
    asm volatile("ldmatrix.sync.aligned.m8n8.x4.shared.b16 {%0,%1,%2,%3}, [%4];"
                 : "=r"(r0), "=r"(r1), "=r"(r2), "=r"(r3) : "r"(addr));
}
__device__ __forceinline__ void mma16816(float* c, const uint32_t* a, const uint32_t* b) {
    asm volatile("mma.sync.aligned.m16n8k16.row.col.f32.bf16.bf16.f32 "
                 "{%0,%1,%2,%3}, {%4,%5,%6,%7}, {%8,%9}, {%0,%1,%2,%3};"
                 : "+f"(c[0]), "+f"(c[1]), "+f"(c[2]), "+f"(c[3])
                 : "r"(a[0]), "r"(a[1]), "r"(a[2]), "r"(a[3]), "r"(b[0]), "r"(b[1]));
}
__device__ __forceinline__ void cp_async16(uint32_t dst, const void* src, int sz) {
    asm volatile("cp.async.cg.shared.global [%0], [%1], 16, %2;"
                 :: "r"(dst), "l"(src), "r"(sz) : "memory");
}
#define CP_COMMIT() asm volatile("cp.async.commit_group;" ::: "memory")
#define CP_WAIT(n)  asm volatile("cp.async.wait_group %0;" :: "n"(n) : "memory")

// --------------------------- bf16 split kernels -----------------------------
__global__ void split4_kernel(const float* __restrict__ X,
                              unsigned short* __restrict__ hi,
                              unsigned short* __restrict__ lo, long n4)
{
    long i = (long)blockIdx.x * blockDim.x + threadIdx.x;
    if (i >= n4) return;
    float4 v = ((const float4*)X)[i];
    ushort4 h, l;
    h.x = __bfloat16_as_ushort(__float2bfloat16_rn(v.x));
    h.y = __bfloat16_as_ushort(__float2bfloat16_rn(v.y));
    h.z = __bfloat16_as_ushort(__float2bfloat16_rn(v.z));
    h.w = __bfloat16_as_ushort(__float2bfloat16_rn(v.w));
    l.x = __bfloat16_as_ushort(__float2bfloat16_rn(v.x - __bfloat162float(__ushort_as_bfloat16(h.x))));
    l.y = __bfloat16_as_ushort(__float2bfloat16_rn(v.y - __bfloat162float(__ushort_as_bfloat16(h.y))));
    l.z = __bfloat16_as_ushort(__float2bfloat16_rn(v.z - __bfloat162float(__ushort_as_bfloat16(h.z))));
    l.w = __bfloat16_as_ushort(__float2bfloat16_rn(v.w - __bfloat162float(__ushort_as_bfloat16(h.w))));
    ((ushort4*)hi)[i] = h;
    ((ushort4*)lo)[i] = l;
}

// W [K,N] fp32 -> hi/lo bf16 [N,K] (transposed, K-major for MMA B operand)
__global__ void splitT_kernel(const float* __restrict__ W,
                              unsigned short* __restrict__ hi,
                              unsigned short* __restrict__ lo, int K, int N)
{
    int idx = blockIdx.x * blockDim.x + threadIdx.x;
    if (idx >= K * N) return;
    int k = idx / N, n = idx - k * N;
    float x = W[idx];
    __nv_bfloat16 h = __float2bfloat16_rn(x);
    __nv_bfloat16 l = __float2bfloat16_rn(x - __bfloat162float(h));
    hi[(size_t)n * K + k] = __bfloat16_as_ushort(h);
    lo[(size_t)n * K + k] = __bfloat16_as_ushort(l);
}

// --------------------------- mma.sync GEMM ----------------------------------
// C[M,N] = A[M,K] @ W[K,N] (+bias). A hi/lo bf16 [M,K]; W hi/lo bf16 [N,K].
// Block tile 128x128, BK=32, 8 warps (warp tile 64x32), 2-stage cp.async.
#define TSTRIDE 40                       // bf16 elems per smem row (80B, conflict-free)
#define TILEB   (128 * TSTRIDE * 2)      // 10240 B per tile
#define STAGEB  (4 * TILEB)              // Ah, Al, Bh, Bl
#define MSMEM   (2 * STAGEB)             // 81920 B

__global__ __launch_bounds__(256, 1)
void bgemm_mma(const unsigned short* __restrict__ Ah, const unsigned short* __restrict__ Al,
               const unsigned short* __restrict__ Bh, const unsigned short* __restrict__ Bl,
               float* __restrict__ C, int M, int N, int K,
               const float* __restrict__ bias)
{
    extern __shared__ char smem[];
    const int tid  = threadIdx.x;
    const int wid  = tid >> 5;
    const int lane = tid & 31;
    const int row0 = blockIdx.y * 128;
    const int col0 = blockIdx.x * 128;
    const int wm   = wid & 1;            // 2 warp rows (64 M each)
    const int wn   = wid >> 1;           // 4 warp cols (32 N each)
    const uint32_t sbase = smem_u32(smem);

    float acc[4][4][4];
#pragma unroll
    for (int mi = 0; mi < 4; mi++)
#pragma unroll
        for (int ni = 0; ni < 4; ni++)
#pragma unroll
            for (int q = 0; q < 4; q++) acc[mi][ni][q] = 0.f;

    const unsigned short* srcs[4] = { Ah, Al, Bh, Bl };

    const int nk = K >> 5;

    // ---- async stage loader: 4 tiles x 128 rows x 4 16B-chunks ----
#define LOAD_STAGE(stage, kc) do {                                            \
        int _k0 = (kc) << 5;                                                  \
        uint32_t _d0 = sbase + (stage) * STAGEB;                              \
        _Pragma("unroll")                                                     \
        for (int _it = 0; _it < 8; _it++) {                                   \
            int _i = tid + (_it << 8);                                        \
            int _t = _i >> 9, _j = _i & 511;                                  \
            int _r = _j >> 2, _ch = _j & 3;                                   \
            int _g = ((_t < 2) ? row0 : col0) + _r;                           \
            int _lim = (_t < 2) ? M : N;                                      \
            int _ok = (_g < _lim);                                            \
            const unsigned short* _s = srcs[_t]                               \
                + (size_t)(_ok ? _g : 0) * K + _k0 + _ch * 8;                 \
            cp_async16(_d0 + _t * TILEB + _r * 80 + _ch * 16, _s, _ok ? 16 : 0); \
        }                                                                     \
        CP_COMMIT();                                                          \
    } while (0)

    LOAD_STAGE(0, 0);

    for (int kc = 0; kc < nk; kc++) {
        const int st = kc & 1;
        if (kc + 1 < nk) { LOAD_STAGE(st ^ 1, kc + 1); CP_WAIT(1); }
        else             { CP_WAIT(0); }
        __syncthreads();

        const uint32_t base = sbase + st * STAGEB;

#pragma unroll
        for (int ks = 0; ks < 2; ks++) {
            // A fragments (hi + lo), 4 m16 tiles
            uint32_t ah[4][4], alo[4][4];
            {
                const int r = lane & 15, ch = lane >> 4;
#pragma unroll
                for (int mi = 0; mi < 4; mi++) {
                    uint32_t addr = base + (wm * 64 + mi * 16 + r) * 80 + ks * 32 + ch * 16;
                    ldsm_x4(ah[mi][0], ah[mi][1], ah[mi][2], ah[mi][3], addr);
                    ldsm_x4(alo[mi][0], alo[mi][1], alo[mi][2], alo[mi][3], addr + TILEB);
                }
            }
            // B fragments (hi + lo), 4 n8 tiles via 2 x4 loads per half
            uint32_t bh[4][2], bl[4][2];
            {
                const int rr   = (lane & 7) + ((lane >> 4) << 3);
                const int kc16 = (lane >> 3) & 1;
#pragma unroll
                for (int n2 = 0; n2 < 2; n2++) {
                    uint32_t addr = base + 2 * TILEB
                                  + (wn * 32 + n2 * 16 + rr) * 80 + ks * 32 + kc16 * 16;
                    uint32_t r0, r1, r2, r3;
                    ldsm_x4(r0, r1, r2, r3, addr);
                    bh[n2 * 2][0] = r0; bh[n2 * 2][1] = r1;
                    bh[n2 * 2 + 1][0] = r2; bh[n2 * 2 + 1][1] = r3;
                    ldsm_x4(r0, r1, r2, r3, addr + TILEB);
                    bl[n2 * 2][0] = r0; bl[n2 * 2][1] = r1;
                    bl[n2 * 2 + 1][0] = r2; bl[n2 * 2 + 1][1] = r3;
                }
            }
            // 3-pass accumulate: hi*hi + hi*lo + lo*hi
#pragma unroll
            for (int mi = 0; mi < 4; mi++)
#pragma unroll
                for (int ni = 0; ni < 4; ni++) {
                    mma16816(acc[mi][ni], ah[mi],  bh[ni]);
                    mma16816(acc[mi][ni], ah[mi],  bl[ni]);
                    mma16816(acc[mi][ni], alo[mi], bh[ni]);
                }
        }
        __syncthreads();
    }

    // ---- epilogue: fragment layout -> global (scalar stores, bounds-safe) ----
    const int g = lane >> 2, t = lane & 3;
#pragma unroll
    for (int mi = 0; mi < 4; mi++) {
        const int r1 = row0 + wm * 64 + mi * 16 + g;
        const int r2 = r1 + 8;
#pragma unroll
        for (int ni = 0; ni < 4; ni++) {
            const int c0 = col0 + wn * 32 + ni * 8 + t * 2;
            const float* a = acc[mi][ni];
            float bz0 = 0.f, bz1 = 0.f;
            if (bias) {
                if (c0 < N)     bz0 = bias[c0];
                if (c0 + 1 < N) bz1 = bias[c0 + 1];
            }
            if (r1 < M) {
                if (c0 < N)     C[(size_t)r1 * N + c0]     = a[0] + bz0;
                if (c0 + 1 < N) C[(size_t)r1 * N + c0 + 1] = a[1] + bz1;
            }
            if (r2 < M) {
                if (c0 < N)     C[(size_t)r2 * N + c0]     = a[2] + bz0;
                if (c0 + 1 < N) C[(size_t)r2 * N + c0 + 1] = a[3] + bz1;
            }
        }
    }
#undef LOAD_STAGE
}

// ------------------------ el / er (attention dots) --------------------------
__global__ void eler_kernel(const float* __restrict__ feat,
                            const float* __restrict__ al,
                            const float* __restrict__ ar,
                            float* __restrict__ el, float* __restrict__ er)
{
    const int n   = blockIdx.x;
    const int tid = threadIdx.x;            // 0..127
    float4 f = *(const float4*)(feat + (size_t)n * FF + tid * 4);
    float4 a = *(const float4*)(al + tid * 4);
    float4 r = *(const float4*)(ar + tid * 4);
    float vl = f.x * a.x + f.y * a.y + f.z * a.z + f.w * a.w;
    float vr = f.x * r.x + f.y * r.y + f.z * r.z + f.w * r.w;
#pragma unroll
    for (int o = 16; o > 0; o >>= 1) {
        vl += __shfl_down_sync(0xffffffffu, vl, o);
        vr += __shfl_down_sync(0xffffffffu, vr, o);
    }
    if ((tid & 31) == 0) {
        int h = tid >> 5;
        el[n * HH + h] = vl;
        er[n * HH + h] = vr;
    }
}

__global__ void fill_neginf(float* __restrict__ p, int n)
{
    int i = blockIdx.x * blockDim.x + threadIdx.x;
    if (i < n) p[i] = -INFINITY;
}

__global__ void edge_max_kernel(const int* __restrict__ src, const int* __restrict__ dst,
                                const float* __restrict__ el, const float* __restrict__ er,
                                float* __restrict__ m, int E)
{
    int e = blockIdx.x * blockDim.x + threadIdx.x;
    if (e >= E) return;
    int s = src[e], d = dst[e];
    float4 l = *(const float4*)(el + s * HH);
    float4 r = *(const float4*)(er + d * HH);
    atomicMaxF(&m[d * HH + 0], leaky02(l.x + r.x));
    atomicMaxF(&m[d * HH + 1], leaky02(l.y + r.y));
    atomicMaxF(&m[d * HH + 2], leaky02(l.z + r.z));
    atomicMaxF(&m[d * HH + 3], leaky02(l.w + r.w));
}

__global__ void edge_expsum_kernel(const int* __restrict__ src, const int* __restrict__ dst,
                                   const float* __restrict__ el, const float* __restrict__ er,
                                   const float* __restrict__ m,
                                   float* __restrict__ w, float* __restrict__ ssum, int E)
{
    int e = blockIdx.x * blockDim.x + threadIdx.x;
    if (e >= E) return;
    int s = src[e], d = dst[e];
    float4 l  = *(const float4*)(el + s * HH);
    float4 r  = *(const float4*)(er + d * HH);
    float4 mx = *(const float4*)(m + d * HH);
    float w0 = expf(leaky02(l.x + r.x) - mx.x);
    float w1 = expf(leaky02(l.y + r.y) - mx.y);
    float w2 = expf(leaky02(l.z + r.z) - mx.z);
    float w3 = expf(leaky02(l.w + r.w) - mx.w);
    *(float4*)(w + (size_t)e * HH) = make_float4(w0, w1, w2, w3);
    atomicAdd(&ssum[d * HH + 0], w0);
    atomicAdd(&ssum[d * HH + 1], w1);
    atomicAdd(&ssum[d * HH + 2], w2);
    atomicAdd(&ssum[d * HH + 3], w3);
}

__global__ void edge_scatter_kernel(const int* __restrict__ src, const int* __restrict__ dst,
                                    const float* __restrict__ feat,
                                    const float* __restrict__ w, const float* __restrict__ ssum,
                                    float* __restrict__ acc, int E)
{
    long long i = (long long)blockIdx.x * blockDim.x + threadIdx.x;
    long long total = (long long)E * 128;
    if (i >= total) return;
    int e = (int)(i >> 7);
    int j = (int)(i & 127);
    int h = j >> 5;
    int s = src[e], d = dst[e];
    float a = w[(size_t)e * HH + h] / ssum[d * HH + h];
    float4 f = *(const float4*)(feat + (size_t)s * FF + j * 4);
    float* o = acc + (size_t)d * FF + j * 4;
    atomicAdd(o + 0, f.x * a);
    atomicAdd(o + 1, f.y * a);
    atomicAdd(o + 2, f.z * a);
    atomicAdd(o + 3, f.w * a);
}

__global__ void combine_kernel(const float* __restrict__ acc0, const float* __restrict__ acc1,
                               const float* __restrict__ b0, const float* __restrict__ b1,
                               float* __restrict__ out, int total, int act)
{
    int i = blockIdx.x * blockDim.x + threadIdx.x;
    if (i >= total) return;
    int j = i & (FF - 1);
    float v0 = acc0[i] + b0[j];
    float v1 = acc1[i] + b1[j];
    if (act) { v0 = leaky01(v0); v1 = leaky01(v1); }
    out[i] = v0 + v1;
}

// ------------------------------ host driver --------------------------------
extern "C" void kernel_launch(void* const* d_in, const int* in_sizes, int n_in,
                              void* d_out, int out_size)
{
    const float* x    = (const float*)d_in[0];
    const int*   srcA[NT] = { (const int*)d_in[1], (const int*)d_in[3] };
    const int*   dstA[NT] = { (const int*)d_in[2], (const int*)d_in[4] };
    const float* W[3]  = { (const float*)d_in[5],  (const float*)d_in[9],  (const float*)d_in[13] };
    const float* al[3] = { (const float*)d_in[6],  (const float*)d_in[10], (const float*)d_in[14] };
    const float* ar[3] = { (const float*)d_in[7],  (const float*)d_in[11], (const float*)d_in[15] };
    const float* bb[3] = { (const float*)d_in[8],  (const float*)d_in[12], (const float*)d_in[16] };
    const float* Wout  = (const float*)d_in[17];
    const float* bout  = (const float*)d_in[18];

    const int E = in_sizes[1];                      // 150000
    const int M = in_sizes[0] / 1024;               // 40000
    const int NOUT = out_size / M;                  // 2983

    cudaFuncSetAttribute(bgemm_mma, cudaFuncAttributeMaxDynamicSharedMemorySize, MSMEM);

    void* p;
    cudaGetSymbolAddress(&p, g_feat); float* feat = (float*)p;
    cudaGetSymbolAddress(&p, g_acc ); float* acc  = (float*)p;
    cudaGetSymbolAddress(&p, g_h   ); float* hbuf = (float*)p;
    cudaGetSymbolAddress(&p, g_el  ); float* el   = (float*)p;
    cudaGetSymbolAddress(&p, g_er  ); float* er   = (float*)p;
    cudaGetSymbolAddress(&p, g_m   ); float* mm   = (float*)p;
    cudaGetSymbolAddress(&p, g_s   ); float* ss   = (float*)p;
    cudaGetSymbolAddress(&p, g_w   ); float* ww   = (float*)p;
    cudaGetSymbolAddress(&p, g_ah  ); unsigned short* ah  = (unsigned short*)p;
    cudaGetSymbolAddress(&p, g_al  ); unsigned short* alo = (unsigned short*)p;
    cudaGetSymbolAddress(&p, g_bth ); unsigned short* bth = (unsigned short*)p;
    cudaGetSymbolAddress(&p, g_btl ); unsigned short* btl = (unsigned short*)p;

    const size_t NF  = (size_t)M * FF;
    const size_t NH4 = (size_t)M * HH;
    const size_t EH4 = (size_t)E * HH;
    const int mtiles = (M + 127) / 128;

    const float* hin = x;
    int K = 1024;

    for (int l = 0; l < 3; l++) {
        // 0) split A into bf16 hi/lo
        {
            long n4 = (long)M * K / 4;
            split4_kernel<<<(int)((n4 + 255) / 256), 256>>>(hin, ah, alo, n4);
        }
        // split+transpose weights
        for (int t = 0; t < NT; t++) {
            int kn = K * FF;
            splitT_kernel<<<(kn + 255) / 256, 256>>>(W[l] + (size_t)t * K * FF,
                                                     bth + (size_t)t * BTS,
                                                     btl + (size_t)t * BTS, K, FF);
        }
        // 1) per-type tensor-core GEMM
        dim3 ggrid(FF / 128, mtiles);
        for (int t = 0; t < NT; t++)
            bgemm_mma<<<ggrid, 256, MSMEM>>>(ah, alo,
                                             bth + (size_t)t * BTS, btl + (size_t)t * BTS,
                                             feat + t * NF, M, FF, K, nullptr);

        // 2) attention dots
        for (int t = 0; t < NT; t++)
            eler_kernel<<<M, 128>>>(feat + t * NF,
                                    al[l] + t * FF, ar[l] + t * FF,
                                    el + t * NH4, er + t * NH4);

        // 3) init reductions
        {
            int n = NT * (int)NH4;
            fill_neginf<<<(n + 255) / 256, 256>>>(mm, n);
            cudaMemsetAsync(ss, 0, (size_t)NT * NH4 * sizeof(float));
            cudaMemsetAsync(acc, 0, (size_t)NT * NF * sizeof(float));
        }

        // 4) edge softmax + scatter
        for (int t = 0; t < NT; t++) {
            int eb = (E + 255) / 256;
            edge_max_kernel<<<eb, 256>>>(srcA[t], dstA[t],
                                         el + t * NH4, er + t * NH4,
                                         mm + t * NH4, E);
            edge_expsum_kernel<<<eb, 256>>>(srcA[t], dstA[t],
                                            el + t * NH4, er + t * NH4,
                                            mm + t * NH4,
                                            ww + t * EH4, ss + t * NH4, E);
            long long tot = (long long)E * 128;
            int sb = (int)((tot + 255) / 256);
            edge_scatter_kernel<<<sb, 256>>>(srcA[t], dstA[t],
                                             feat + t * NF,
                                             ww + t * EH4, ss + t * NH4,
                                             acc + t * NF, E);
        }

        // 5) combine
        {
            int total = (int)NF;
            combine_kernel<<<(total + 255) / 256, 256>>>(
                acc, acc + NF, bb[l], bb[l] + FF, hbuf, total, l < 2 ? 1 : 0);
        }

        hin = hbuf;
        K = FF;
    }

    // final projection on tensor cores
    {
        long n4 = (long)M * FF / 4;
        split4_kernel<<<(int)((n4 + 255) / 256), 256>>>(hbuf, ah, alo, n4);
        int kn = FF * NOUT;
        splitT_kernel<<<(kn + 255) / 256, 256>>>(Wout, bth, btl, FF, NOUT);
        dim3 fgrid((NOUT + 127) / 128, mtiles);
        bgemm_mma<<<fgrid, 256, MSMEM>>>(ah, alo, bth, btl,
                                         (float*)d_out, M, NOUT, FF, bout);
    }
}

// round 14
// speedup vs baseline: 2.3113x; 1.1207x over previous
#include <cuda_runtime.h>
#include <cuda_bf16.h>
#include <math.h>
#include <stdint.h>

// ---------------------------------------------------------------------------
// RGAT (DGL-style), 3 hetero layers x 2 edge types of GATConv (H=4, D=128),
// then final linear [512 -> 2983].
// Round 14 (= Round 10 resubmit; repeated infra timeouts): 3-stage cp.async
// pipeline + red.v4 scatter; scalar epilogue (float2 stores trapped on the
// odd-N=2983 final GEMM).
// ---------------------------------------------------------------------------

#define NN     40000
#define EE     150000
#define HH     4
#define FF     512
#define NT     2
#define BTS    1527296        // transposed-weight buffer stride (2983*512 max)

// ------------------------- scratch (device globals) ------------------------
__device__ float g_feat[NT * NN * FF];
__device__ float g_acc [NT * NN * FF];
__device__ float g_h   [NN * FF];
__device__ float g_el  [NT * NN * HH];
__device__ float g_er  [NT * NN * HH];
__device__ float g_m   [NT * NN * HH];
__device__ float g_s   [NT * NN * HH];
__device__ float g_w   [NT * EE * HH];
__device__ unsigned short g_ah[NN * 1024];   // A hi (bf16 bits), K-major
__device__ unsigned short g_al[NN * 1024];   // A lo
__device__ unsigned short g_bth[NT * BTS];   // B^T hi  [N,K]
__device__ unsigned short g_btl[NT * BTS];   // B^T lo

// ------------------------------ helpers ------------------------------------
__device__ __forceinline__ float leaky02(float x) { return x > 0.f ? x : 0.2f * x; }
__device__ __forceinline__ float leaky01(float x) { return x > 0.f ? x : 0.01f * x; }
__device__ __forceinline__ void atomicMaxF(float* addr, float v) {
    if (v >= 0.f) atomicMax((int*)addr, __float_as_int(v));
    else          atomicMin((unsigned int*)addr, __float_as_uint(v));
}
__device__ __forceinline__ uint32_t smem_u32(const void* p) {
    uint32_t a;
    asm("{ .reg .u64 t; cvta.to.shared.u64 t, %1; cvt.u32.u64 %0, t; }"
        : "=r"(a) : "l"(p));
    return a;
}

// ------------------------ mma / ldmatrix / cp.async -------------------------
__device__ __forceinline__ void ldsm_x4(uint32_t& r0, uint32_t& r1,
                                        uint32_t& r2, uint32_t& r3, uint32_t addr) {
    asm volatile("ldmatrix.sync.aligned.m8n8.x4.shared.b16 {%0,%1,%2,%3}, [%4];"
                 : "=r"(r0), "=r"(r1), "=r"(r2), "=r"(r3) : "r"(addr));
}
__device__ __forceinline__ void mma16816(float* c, const uint32_t* a, const uint32_t* b) {
    asm volatile("mma.sync.aligned.m16n8k16.row.col.f32.bf16.bf16.f32 "
                 "{%0,%1,%2,%3}, {%4,%5,%6,%7}, {%8,%9}, {%0,%1,%2,%3};"
                 : "+f"(c[0]), "+f"(c[1]), "+f"(c[2]), "+f"(c[3])
                 : "r"(a[0]), "r"(a[1]), "r"(a[2]), "r"(a[3]), "r"(b[0]), "r"(b[1]));
}
__device__ __forceinline__ void cp_async16(uint32_t dst, const void* src, int sz) {
    asm volatile("cp.async.cg.shared.global [%0], [%1], 16, %2;"
                 :: "r"(dst), "l"(src), "r"(sz) : "memory");
}
#define CP_COMMIT() asm volatile("cp.async.commit_group;" ::: "memory")
#define CP_WAIT(n)  asm volatile("cp.async.wait_group %0;" :: "n"(n) : "memory")

// --------------------------- bf16 split kernels -----------------------------
__global__ void split4_kernel(const float* __restrict__ X,
                              unsigned short* __restrict__ hi,
                              unsigned short* __restrict__ lo, long n4)
{
    long i = (long)blockIdx.x * blockDim.x + threadIdx.x;
    if (i >= n4) return;
    float4 v = ((const float4*)X)[i];
    ushort4 h, l;
    h.x = __bfloat16_as_ushort(__float2bfloat16_rn(v.x));
    h.y = __bfloat16_as_ushort(__float2bfloat16_rn(v.y));
    h.z = __bfloat16_as_ushort(__float2bfloat16_rn(v.z));
    h.w = __bfloat16_as_ushort(__float2bfloat16_rn(v.w));
    l.x = __bfloat16_as_ushort(__float2bfloat16_rn(v.x - __bfloat162float(__ushort_as_bfloat16(h.x))));
    l.y = __bfloat16_as_ushort(__float2bfloat16_rn(v.y - __bfloat162float(__ushort_as_bfloat16(h.y))));
    l.z = __bfloat16_as_ushort(__float2bfloat16_rn(v.z - __bfloat162float(__ushort_as_bfloat16(h.z))));
    l.w = __bfloat16_as_ushort(__float2bfloat16_rn(v.w - __bfloat162float(__ushort_as_bfloat16(h.w))));
    ((ushort4*)hi)[i] = h;
    ((ushort4*)lo)[i] = l;
}

// W [K,N] fp32 -> hi/lo bf16 [N,K] (transposed, K-major for MMA B operand)
__global__ void splitT_kernel(const float* __restrict__ W,
                              unsigned short* __restrict__ hi,
                              unsigned short* __restrict__ lo, int K, int N)
{
    int idx = blockIdx.x * blockDim.x + threadIdx.x;
    if (idx >= K * N) return;
    int k = idx / N, n = idx - k * N;
    float x = W[idx];
    __nv_bfloat16 h = __float2bfloat16_rn(x);
    __nv_bfloat16 l = __float2bfloat16_rn(x - __bfloat162float(h));
    hi[(size_t)n * K + k] = __bfloat16_as_ushort(h);
    lo[(size_t)n * K + k] = __bfloat16_as_ushort(l);
}

// --------------------------- mma.sync GEMM ----------------------------------
// C[M,N] = A[M,K] @ W[K,N] (+bias). A hi/lo bf16 [M,K]; W hi/lo bf16 [N,K].
// Block tile 128x128, BK=32, 8 warps (warp tile 64x32), 3-stage cp.async.
#define TSTRIDE 40                       // bf16 elems per smem row (80B, conflict-free)
#define TILEB   (128 * TSTRIDE * 2)      // 10240 B per tile
#define STAGEB  (4 * TILEB)              // Ah, Al, Bh, Bl
#define NSTAGE  3
#define MSMEM   (NSTAGE * STAGEB)        // 122880 B

__global__ __launch_bounds__(256, 1)
void bgemm_mma(const unsigned short* __restrict__ Ah, const unsigned short* __restrict__ Al,
               const unsigned short* __restrict__ Bh, const unsigned short* __restrict__ Bl,
               float* __restrict__ C, int M, int N, int K,
               const float* __restrict__ bias)
{
    extern __shared__ char smem[];
    const int tid  = threadIdx.x;
    const int wid  = tid >> 5;
    const int lane = tid & 31;
    const int row0 = blockIdx.y * 128;
    const int col0 = blockIdx.x * 128;
    const int wm   = wid & 1;            // 2 warp rows (64 M each)
    const int wn   = wid >> 1;           // 4 warp cols (32 N each)
    const uint32_t sbase = smem_u32(smem);

    float acc[4][4][4];
#pragma unroll
    for (int mi = 0; mi < 4; mi++)
#pragma unroll
        for (int ni = 0; ni < 4; ni++)
#pragma unroll
            for (int q = 0; q < 4; q++) acc[mi][ni][q] = 0.f;

    const unsigned short* srcs[4] = { Ah, Al, Bh, Bl };

    const int nk = K >> 5;

    // ---- async stage loader: 4 tiles x 128 rows x 4 16B-chunks ----
#define LOAD_STAGE(stage, kc) do {                                            \
        int _k0 = (kc) << 5;                                                  \
        uint32_t _d0 = sbase + (stage) * STAGEB;                              \
        _Pragma("unroll")                                                     \
        for (int _it = 0; _it < 8; _it++) {                                   \
            int _i = tid + (_it << 8);                                        \
            int _t = _i >> 9, _j = _i & 511;                                  \
            int _r = _j >> 2, _ch = _j & 3;                                   \
            int _g = ((_t < 2) ? row0 : col0) + _r;                           \
            int _lim = (_t < 2) ? M : N;                                      \
            int _ok = (_g < _lim);                                            \
            const unsigned short* _s = srcs[_t]                               \
                + (size_t)(_ok ? _g : 0) * K + _k0 + _ch * 8;                 \
            cp_async16(_d0 + _t * TILEB + _r * 80 + _ch * 16, _s, _ok ? 16 : 0); \
        }                                                                     \
    } while (0)

    // prologue: stages 0 and 1 (nk >= 2 always here)
    LOAD_STAGE(0, 0); CP_COMMIT();
    LOAD_STAGE(1, 1); CP_COMMIT();

    int st = 0;
    for (int kc = 0; kc < nk; kc++) {
        CP_WAIT(1);              // group kc complete (<=1 newer pending)
        __syncthreads();         // visible to all warps; prev readers done

        // prefetch kc+2 into the stage last read at kc-1
        if (kc + 2 < nk) {
            int st2 = st + 2; if (st2 >= NSTAGE) st2 -= NSTAGE;
            LOAD_STAGE(st2, kc + 2);
        }
        CP_COMMIT();             // commit every iteration (possibly empty)

        const uint32_t base = sbase + st * STAGEB;

#pragma unroll
        for (int ks = 0; ks < 2; ks++) {
            // A fragments (hi + lo), 4 m16 tiles
            uint32_t ah[4][4], alo[4][4];
            {
                const int r = lane & 15, ch = lane >> 4;
#pragma unroll
                for (int mi = 0; mi < 4; mi++) {
                    uint32_t addr = base + (wm * 64 + mi * 16 + r) * 80 + ks * 32 + ch * 16;
                    ldsm_x4(ah[mi][0], ah[mi][1], ah[mi][2], ah[mi][3], addr);
                    ldsm_x4(alo[mi][0], alo[mi][1], alo[mi][2], alo[mi][3], addr + TILEB);
                }
            }
            // B fragments (hi + lo), 4 n8 tiles via 2 x4 loads per half
            uint32_t bh[4][2], bl[4][2];
            {
                const int rr   = (lane & 7) + ((lane >> 4) << 3);
                const int kc16 = (lane >> 3) & 1;
#pragma unroll
                for (int n2 = 0; n2 < 2; n2++) {
                    uint32_t addr = base + 2 * TILEB
                                  + (wn * 32 + n2 * 16 + rr) * 80 + ks * 32 + kc16 * 16;
                    uint32_t r0, r1, r2, r3;
                    ldsm_x4(r0, r1, r2, r3, addr);
                    bh[n2 * 2][0] = r0; bh[n2 * 2][1] = r1;
                    bh[n2 * 2 + 1][0] = r2; bh[n2 * 2 + 1][1] = r3;
                    ldsm_x4(r0, r1, r2, r3, addr + TILEB);
                    bl[n2 * 2][0] = r0; bl[n2 * 2][1] = r1;
                    bl[n2 * 2 + 1][0] = r2; bl[n2 * 2 + 1][1] = r3;
                }
            }
            // 3-pass accumulate: hi*hi + hi*lo + lo*hi
#pragma unroll
            for (int mi = 0; mi < 4; mi++)
#pragma unroll
                for (int ni = 0; ni < 4; ni++) {
                    mma16816(acc[mi][ni], ah[mi],  bh[ni]);
                    mma16816(acc[mi][ni], ah[mi],  bl[ni]);
                    mma16816(acc[mi][ni], alo[mi], bh[ni]);
                }
        }
        st++; if (st >= NSTAGE) st = 0;
    }

    // ---- epilogue: fragment layout -> global (scalar stores, alignment-safe) ----
    const int g = lane >> 2, t = lane & 3;
#pragma unroll
    for (int mi = 0; mi < 4; mi++) {
        const int r1 = row0 + wm * 64 + mi * 16 + g;
        const int r2 = r1 + 8;
#pragma unroll
        for (int ni = 0; ni < 4; ni++) {
            const int c0 = col0 + wn * 32 + ni * 8 + t * 2;
            const float* a = acc[mi][ni];
            float bz0 = 0.f, bz1 = 0.f;
            if (bias) {
                if (c0 < N)     bz0 = bias[c0];
                if (c0 + 1 < N) bz1 = bias[c0 + 1];
            }
            if (r1 < M) {
                if (c0 < N)     C[(size_t)r1 * N + c0]     = a[0] + bz0;
                if (c0 + 1 < N) C[(size_t)r1 * N + c0 + 1] = a[1] + bz1;
            }
            if (r2 < M) {
                if (c0 < N)     C[(size_t)r2 * N + c0]     = a[2] + bz0;
                if (c0 + 1 < N) C[(size_t)r2 * N + c0 + 1] = a[3] + bz1;
            }
        }
    }
#undef LOAD_STAGE
}

// ------------------------ el / er (attention dots) --------------------------
__global__ void eler_kernel(const float* __restrict__ feat,
                            const float* __restrict__ al,
                            const float* __restrict__ ar,
                            float* __restrict__ el, float* __restrict__ er)
{
    const int n   = blockIdx.x;
    const int tid = threadIdx.x;            // 0..127
    float4 f = *(const float4*)(feat + (size_t)n * FF + tid * 4);
    float4 a = *(const float4*)(al + tid * 4);
    float4 r = *(const float4*)(ar + tid * 4);
    float vl = f.x * a.x + f.y * a.y + f.z * a.z + f.w * a.w;
    float vr = f.x * r.x + f.y * r.y + f.z * r.z + f.w * r.w;
#pragma unroll
    for (int o = 16; o > 0; o >>= 1) {
        vl += __shfl_down_sync(0xffffffffu, vl, o);
        vr += __shfl_down_sync(0xffffffffu, vr, o);
    }
    if ((tid & 31) == 0) {
        int h = tid >> 5;
        el[n * HH + h] = vl;
        er[n * HH + h] = vr;
    }
}

__global__ void fill_neginf(float* __restrict__ p, int n)
{
    int i = blockIdx.x * blockDim.x + threadIdx.x;
    if (i < n) p[i] = -INFINITY;
}

__global__ void edge_max_kernel(const int* __restrict__ src, const int* __restrict__ dst,
                                const float* __restrict__ el, const float* __restrict__ er,
                                float* __restrict__ m, int E)
{
    int e = blockIdx.x * blockDim.x + threadIdx.x;
    if (e >= E) return;
    int s = src[e], d = dst[e];
    float4 l = *(const float4*)(el + s * HH);
    float4 r = *(const float4*)(er + d * HH);
    atomicMaxF(&m[d * HH + 0], leaky02(l.x + r.x));
    atomicMaxF(&m[d * HH + 1], leaky02(l.y + r.y));
    atomicMaxF(&m[d * HH + 2], leaky02(l.z + r.z));
    atomicMaxF(&m[d * HH + 3], leaky02(l.w + r.w));
}

__global__ void edge_expsum_kernel(const int* __restrict__ src, const int* __restrict__ dst,
                                   const float* __restrict__ el, const float* __restrict__ er,
                                   const float* __restrict__ m,
                                   float* __restrict__ w, float* __restrict__ ssum, int E)
{
    int e = blockIdx.x * blockDim.x + threadIdx.x;
    if (e >= E) return;
    int s = src[e], d = dst[e];
    float4 l  = *(const float4*)(el + s * HH);
    float4 r  = *(const float4*)(er + d * HH);
    float4 mx = *(const float4*)(m + d * HH);
    float w0 = expf(leaky02(l.x + r.x) - mx.x);
    float w1 = expf(leaky02(l.y + r.y) - mx.y);
    float w2 = expf(leaky02(l.z + r.z) - mx.z);
    float w3 = expf(leaky02(l.w + r.w) - mx.w);
    *(float4*)(w + (size_t)e * HH) = make_float4(w0, w1, w2, w3);
    atomicAdd(&ssum[d * HH + 0], w0);
    atomicAdd(&ssum[d * HH + 1], w1);
    atomicAdd(&ssum[d * HH + 2], w2);
    atomicAdd(&ssum[d * HH + 3], w3);
}

__global__ void edge_scatter_kernel(const int* __restrict__ src, const int* __restrict__ dst,
                                    const float* __restrict__ feat,
                                    const float* __restrict__ w, const float* __restrict__ ssum,
                                    float* __restrict__ acc, int E)
{
    long long i = (long long)blockIdx.x * blockDim.x + threadIdx.x;
    long long total = (long long)E * 128;
    if (i >= total) return;
    int e = (int)(i >> 7);
    int j = (int)(i & 127);
    int h = j >> 5;
    int s = src[e], d = dst[e];
    float a = w[(size_t)e * HH + h] / ssum[d * HH + h];
    float4 f = *(const float4*)(feat + (size_t)s * FF + j * 4);
    float* o = acc + (size_t)d * FF + j * 4;
    asm volatile("red.global.add.v4.f32 [%0], {%1, %2, %3, %4};"
                 :: "l"(o), "f"(f.x * a), "f"(f.y * a), "f"(f.z * a), "f"(f.w * a)
                 : "memory");
}

__global__ void combine_kernel(const float* __restrict__ acc0, const float* __restrict__ acc1,
                               const float* __restrict__ b0, const float* __restrict__ b1,
                               float* __restrict__ out, int total, int act)
{
    int i = blockIdx.x * blockDim.x + threadIdx.x;
    if (i >= total) return;
    int j = i & (FF - 1);
    float v0 = acc0[i] + b0[j];
    float v1 = acc1[i] + b1[j];
    if (act) { v0 = leaky01(v0); v1 = leaky01(v1); }
    out[i] = v0 + v1;
}

// ------------------------------ host driver --------------------------------
extern "C" void kernel_launch(void* const* d_in, const int* in_sizes, int n_in,
                              void* d_out, int out_size)
{
    const float* x    = (const float*)d_in[0];
    const int*   srcA[NT] = { (const int*)d_in[1], (const int*)d_in[3] };
    const int*   dstA[NT] = { (const int*)d_in[2], (const int*)d_in[4] };
    const float* W[3]  = { (const float*)d_in[5],  (const float*)d_in[9],  (const float*)d_in[13] };
    const float* al[3] = { (const float*)d_in[6],  (const float*)d_in[10], (const float*)d_in[14] };
    const float* ar[3] = { (const float*)d_in[7],  (const float*)d_in[11], (const float*)d_in[15] };
    const float* bb[3] = { (const float*)d_in[8],  (const float*)d_in[12], (const float*)d_in[16] };
    const float* Wout  = (const float*)d_in[17];
    const float* bout  = (const float*)d_in[18];

    const int E = in_sizes[1];                      // 150000
    const int M = in_sizes[0] / 1024;               // 40000
    const int NOUT = out_size / M;                  // 2983

    cudaFuncSetAttribute(bgemm_mma, cudaFuncAttributeMaxDynamicSharedMemorySize, MSMEM);

    void* p;
    cudaGetSymbolAddress(&p, g_feat); float* feat = (float*)p;
    cudaGetSymbolAddress(&p, g_acc ); float* acc  = (float*)p;
    cudaGetSymbolAddress(&p, g_h   ); float* hbuf = (float*)p;
    cudaGetSymbolAddress(&p, g_el  ); float* el   = (float*)p;
    cudaGetSymbolAddress(&p, g_er  ); float* er   = (float*)p;
    cudaGetSymbolAddress(&p, g_m   ); float* mm   = (float*)p;
    cudaGetSymbolAddress(&p, g_s   ); float* ss   = (float*)p;
    cudaGetSymbolAddress(&p, g_w   ); float* ww   = (float*)p;
    cudaGetSymbolAddress(&p, g_ah  ); unsigned short* ah  = (unsigned short*)p;
    cudaGetSymbolAddress(&p, g_al  ); unsigned short* alo = (unsigned short*)p;
    cudaGetSymbolAddress(&p, g_bth ); unsigned short* bth = (unsigned short*)p;
    cudaGetSymbolAddress(&p, g_btl ); unsigned short* btl = (unsigned short*)p;

    const size_t NF  = (size_t)M * FF;
    const size_t NH4 = (size_t)M * HH;
    const size_t EH4 = (size_t)E * HH;
    const int mtiles = (M + 127) / 128;

    const float* hin = x;
    int K = 1024;

    for (int l = 0; l < 3; l++) {
        // 0) split A into bf16 hi/lo
        {
            long n4 = (long)M * K / 4;
            split4_kernel<<<(int)((n4 + 255) / 256), 256>>>(hin, ah, alo, n4);
        }
        // split+transpose weights
        for (int t = 0; t < NT; t++) {
            int kn = K * FF;
            splitT_kernel<<<(kn + 255) / 256, 256>>>(W[l] + (size_t)t * K * FF,
                                                     bth + (size_t)t * BTS,
                                                     btl + (size_t)t * BTS, K, FF);
        }
        // 1) per-type tensor-core GEMM
        dim3 ggrid(FF / 128, mtiles);
        for (int t = 0; t < NT; t++)
            bgemm_mma<<<ggrid, 256, MSMEM>>>(ah, alo,
                                             bth + (size_t)t * BTS, btl + (size_t)t * BTS,
                                             feat + t * NF, M, FF, K, nullptr);

        // 2) attention dots
        for (int t = 0; t < NT; t++)
            eler_kernel<<<M, 128>>>(feat + t * NF,
                                    al[l] + t * FF, ar[l] + t * FF,
                                    el + t * NH4, er + t * NH4);

        // 3) init reductions
        {
            int n = NT * (int)NH4;
            fill_neginf<<<(n + 255) / 256, 256>>>(mm, n);
            cudaMemsetAsync(ss, 0, (size_t)NT * NH4 * sizeof(float));
            cudaMemsetAsync(acc, 0, (size_t)NT * NF * sizeof(float));
        }

        // 4) edge softmax + scatter
        for (int t = 0; t < NT; t++) {
            int eb = (E + 255) / 256;
            edge_max_kernel<<<eb, 256>>>(srcA[t], dstA[t],
                                         el + t * NH4, er + t * NH4,
                                         mm + t * NH4, E);
            edge_expsum_kernel<<<eb, 256>>>(srcA[t], dstA[t],
                                            el + t * NH4, er + t * NH4,
                                            mm + t * NH4,
                                            ww + t * EH4, ss + t * NH4, E);
            long long tot = (long long)E * 128;
            int sb = (int)((tot + 255) / 256);
            edge_scatter_kernel<<<sb, 256>>>(srcA[t], dstA[t],
                                             feat + t * NF,
                                             ww + t * EH4, ss + t * NH4,
                                             acc + t * NF, E);
        }

        // 5) combine
        {
            int total = (int)NF;
            combine_kernel<<<(total + 255) / 256, 256>>>(
                acc, acc + NF, bb[l], bb[l] + FF, hbuf, total, l < 2 ? 1 : 0);
        }

        hin = hbuf;
        K = FF;
    }

    // final projection on tensor cores
    {
        long n4 = (long)M * FF / 4;
        split4_kernel<<<(int)((n4 + 255) / 256), 256>>>(hbuf, ah, alo, n4);
        int kn = FF * NOUT;
        splitT_kernel<<<(kn + 255) / 256, 256>>>(Wout, bth, btl, FF, NOUT);
        dim3 fgrid((NOUT + 127) / 128, mtiles);
        bgemm_mma<<<fgrid, 256, MSMEM>>>(ah, alo, bth, btl,
                                         (float*)d_out, M, NOUT, FF, bout);
    }
}